// round 7
// baseline (speedup 1.0000x reference)
#include <cuda_runtime.h>
#include <cuda_bf16.h>

// LBP uniform (P=8, R=1) over (B,C,H,W)=(32,3,512,512) float32.
// R7 = R6 with the PRMT bug fixed: __byte_perm masks off the msb-replicate
// selector bits, so sign-gather must use inline-PTX prmt.b32 (generic mode
// honors selector nibbles 0x8-0xF = replicate MSB of selected byte).
//  - integer compares: n>=c via sign of bits(n)-bits(c) (non-neg floats)
//  - 3x prmt gathers 8 sign bytes into two regs; signed DP4A (weights
//    1,2,4,8; acc 15) converts sign bytes (-1/0) into LBP code nibbles
//  - per-warp register LUT (8 nibbles/lane) + SHFL for the uniform-LBP tail
//  - grid-stride: 8 tasks/warp amortizes LUT setup + indexing

#define IMG_W 512
#define IMG_H 512

__device__ __forceinline__ unsigned prmt(unsigned a, unsigned b, unsigned sel) {
    unsigned d;
    asm("prmt.b32 %0, %1, %2, %3;" : "=r"(d) : "r"(a), "r"(b), "r"(sel));
    return d;
}

__global__ __launch_bounds__(256)
void lbp_kernel(const float* __restrict__ x, float* __restrict__ out,
                int ntasks, int totalWarps) {
    const int lane = threadIdx.x & 31;

    // Register LUT: lane k holds LBP(8k+j) in nibble j (values 0..9).
    unsigned lutv = 0;
#pragma unroll
    for (int j = 0; j < 8; j++) {
        const unsigned m = (unsigned)(lane * 8 + j);
        const unsigned rot = ((m << 1) | (m >> 7)) & 0xFFu;
        const int trans = __popc(m ^ rot);
        const int ones  = __popc(m);
        const unsigned v = (trans <= 2) ? (unsigned)ones : 9u;
        lutv |= v << (4 * j);
    }

    const int wg0 = blockIdx.x * (blockDim.x >> 5) + (threadIdx.x >> 5);

    for (int task = wg0; task < ntasks; task += totalWarps) {
        const int r = task >> 1;          // flattened row over B*C*H
        const int s = task & 1;           // 256-col segment
        const int h = r & (IMG_H - 1);
        const bool hasTop = (h != 0);
        const bool hasBot = (h != IMG_H - 1);

        const float* rowc = x + (size_t)r * IMG_W + s * 256;
        const float* rowt = rowc - IMG_W;
        const float* rowb = rowc + IMG_W;
        const int col = lane * 8;

        const float4 z4 = make_float4(0.f, 0.f, 0.f, 0.f);
        float4 c4a = *reinterpret_cast<const float4*>(rowc + col);
        float4 c4b = *reinterpret_cast<const float4*>(rowc + col + 4);
        float4 t4a = hasTop ? *reinterpret_cast<const float4*>(rowt + col)     : z4;
        float4 t4b = hasTop ? *reinterpret_cast<const float4*>(rowt + col + 4) : z4;
        float4 b4a = hasBot ? *reinterpret_cast<const float4*>(rowb + col)     : z4;
        float4 b4b = hasBot ? *reinterpret_cast<const float4*>(rowb + col + 4) : z4;

        // scaled (x*255): [0]=left halo, [1..8]=own, [9]=right halo
        float qc[10], qt[10], qb[10];
        qc[1]=c4a.x*255.f; qc[2]=c4a.y*255.f; qc[3]=c4a.z*255.f; qc[4]=c4a.w*255.f;
        qc[5]=c4b.x*255.f; qc[6]=c4b.y*255.f; qc[7]=c4b.z*255.f; qc[8]=c4b.w*255.f;
        qt[1]=t4a.x*255.f; qt[2]=t4a.y*255.f; qt[3]=t4a.z*255.f; qt[4]=t4a.w*255.f;
        qt[5]=t4b.x*255.f; qt[6]=t4b.y*255.f; qt[7]=t4b.z*255.f; qt[8]=t4b.w*255.f;
        qb[1]=b4a.x*255.f; qb[2]=b4a.y*255.f; qb[3]=b4a.z*255.f; qb[4]=b4a.w*255.f;
        qb[5]=b4b.x*255.f; qb[6]=b4b.y*255.f; qb[7]=b4b.z*255.f; qb[8]=b4b.w*255.f;

        qc[0] = __shfl_up_sync(0xFFFFFFFFu, qc[8], 1);
        qt[0] = __shfl_up_sync(0xFFFFFFFFu, qt[8], 1);
        qb[0] = __shfl_up_sync(0xFFFFFFFFu, qb[8], 1);
        qc[9] = __shfl_down_sync(0xFFFFFFFFu, qc[1], 1);
        qt[9] = __shfl_down_sync(0xFFFFFFFFu, qt[1], 1);
        qb[9] = __shfl_down_sync(0xFFFFFFFFu, qb[1], 1);

        if (lane == 0) {
            const bool hasLeft = (s != 0);
            qc[0] = hasLeft ? rowc[-1] * 255.f : 0.f;
            qt[0] = (hasLeft && hasTop) ? rowt[-1] * 255.f : 0.f;
            qb[0] = (hasLeft && hasBot) ? rowb[-1] * 255.f : 0.f;
        }
        if (lane == 31) {
            const bool hasRight = (s != 1);
            qc[9] = hasRight ? rowc[256] * 255.f : 0.f;
            qt[9] = (hasRight && hasTop) ? rowt[256] * 255.f : 0.f;
            qb[9] = (hasRight && hasBot) ? rowb[256] * 255.f : 0.f;
        }

        float res[8];
#pragma unroll
        for (int j = 0; j < 8; j++) {
            // centers: floor(u)>=floor(v) <=> u>=floor(v); all values >= 0,
            // so the float compare equals the integer compare of bit patterns.
            const int bc = __float_as_int(floorf(qc[j + 1]));
            // circular order bits 0..7: tl, t, tr, r, br, b, bl, l
            const unsigned d0 = (unsigned)(__float_as_int(qt[j    ]) - bc);
            const unsigned d1 = (unsigned)(__float_as_int(qt[j + 1]) - bc);
            const unsigned d2 = (unsigned)(__float_as_int(qt[j + 2]) - bc);
            const unsigned d3 = (unsigned)(__float_as_int(qc[j + 2]) - bc);
            const unsigned d4 = (unsigned)(__float_as_int(qb[j + 2]) - bc);
            const unsigned d5 = (unsigned)(__float_as_int(qb[j + 1]) - bc);
            const unsigned d6 = (unsigned)(__float_as_int(qb[j    ]) - bc);
            const unsigned d7 = (unsigned)(__float_as_int(qc[j    ]) - bc);
            // prmt sign-replicate: byte = 0xFF where diff<0 (neighbor<center)
            const unsigned sA = prmt(prmt(d0, d1, 0x00FBu),
                                     prmt(d2, d3, 0xFB00u), 0x7610u);
            const unsigned sB = prmt(prmt(d4, d5, 0x00FBu),
                                     prmt(d6, d7, 0xFB00u), 0x7610u);
            // signed dp4a: sign bytes are -1; nibble = 15 - sum(sign*2^i)
            const int mlo = __dp4a((int)sA, 0x08040201, 0x0F);
            const int mhi = __dp4a((int)sB, 0x08040201, 0x0F);
            const unsigned m = (unsigned)mlo | ((unsigned)mhi << 4);
            // register-LUT lookup via shuffle
            const unsigned lv  = __shfl_sync(0xFFFFFFFFu, lutv, (int)(m >> 3));
            const unsigned nib = (lv >> ((m & 7u) << 2)) & 0xFu;
            res[j] = (float)nib * (1.0f / 255.0f);
        }

        float* op = out + (size_t)r * IMG_W + s * 256 + col;
        *reinterpret_cast<float4*>(op)     = make_float4(res[0], res[1], res[2], res[3]);
        *reinterpret_cast<float4*>(op + 4) = make_float4(res[4], res[5], res[6], res[7]);
    }
}

extern "C" void kernel_launch(void* const* d_in, const int* in_sizes, int n_in,
                              void* d_out, int out_size) {
    const float* x = (const float*)d_in[0];
    float* out = (float*)d_out;
    const int nrows  = out_size / IMG_W;   // B*C*H
    const int ntasks = nrows * 2;          // 2 segments of 256 cols per row
    const int threads = 256;               // 8 warps/block
    const int blocks = 1536;               // 12288 warps -> 8 tasks/warp
    const int totalWarps = blocks * (threads / 32);
    lbp_kernel<<<blocks, threads>>>(x, out, ntasks, totalWarps);
}

// round 8
// speedup vs baseline: 1.0454x; 1.0454x over previous
#include <cuda_runtime.h>
#include <cuda_bf16.h>

// LBP uniform (P=8, R=1) over (B,C,H,W)=(32,3,512,512) float32.
// R8 = R4 launch structure (plain grid, 8px/thread, 256-col warp segments)
//    + R7's integer-compare / prmt-sign-gather / dp4a code construction
//    + pure-arithmetic tail (no shuffle LUT, no shared mem, no grid-stride).
// Rationale: kernel is instruction-count bound (no pipe saturated, issue~70%);
// this drops static count ~14% vs R4 and keeps all tail ops on low-latency ALU.

#define IMG_W 512
#define IMG_H 512

__device__ __forceinline__ unsigned prmt(unsigned a, unsigned b, unsigned sel) {
    unsigned d;
    asm("prmt.b32 %0, %1, %2, %3;" : "=r"(d) : "r"(a), "r"(b), "r"(sel));
    return d;
}

__global__ __launch_bounds__(256)
void lbp_kernel(const float* __restrict__ x, float* __restrict__ out, int nrows) {
    const int warpG = blockIdx.x * (blockDim.x >> 5) + (threadIdx.x >> 5);
    const int lane  = threadIdx.x & 31;
    const int r = warpG >> 1;        // flattened row over B*C*H
    const int s = warpG & 1;         // 256-col segment
    if (r >= nrows) return;

    const int h = r & (IMG_H - 1);
    const bool hasTop = (h != 0);
    const bool hasBot = (h != IMG_H - 1);

    const float* rowc = x + (size_t)r * IMG_W + s * 256;
    const float* rowt = rowc - IMG_W;
    const float* rowb = rowc + IMG_W;
    const int col = lane * 8;

    const float4 z4 = make_float4(0.f, 0.f, 0.f, 0.f);
    float4 c4a = *reinterpret_cast<const float4*>(rowc + col);
    float4 c4b = *reinterpret_cast<const float4*>(rowc + col + 4);
    float4 t4a = hasTop ? *reinterpret_cast<const float4*>(rowt + col)     : z4;
    float4 t4b = hasTop ? *reinterpret_cast<const float4*>(rowt + col + 4) : z4;
    float4 b4a = hasBot ? *reinterpret_cast<const float4*>(rowb + col)     : z4;
    float4 b4b = hasBot ? *reinterpret_cast<const float4*>(rowb + col + 4) : z4;

    // scaled (x*255): [0]=left halo, [1..8]=own, [9]=right halo
    float qc[10], qt[10], qb[10];
    qc[1]=c4a.x*255.f; qc[2]=c4a.y*255.f; qc[3]=c4a.z*255.f; qc[4]=c4a.w*255.f;
    qc[5]=c4b.x*255.f; qc[6]=c4b.y*255.f; qc[7]=c4b.z*255.f; qc[8]=c4b.w*255.f;
    qt[1]=t4a.x*255.f; qt[2]=t4a.y*255.f; qt[3]=t4a.z*255.f; qt[4]=t4a.w*255.f;
    qt[5]=t4b.x*255.f; qt[6]=t4b.y*255.f; qt[7]=t4b.z*255.f; qt[8]=t4b.w*255.f;
    qb[1]=b4a.x*255.f; qb[2]=b4a.y*255.f; qb[3]=b4a.z*255.f; qb[4]=b4a.w*255.f;
    qb[5]=b4b.x*255.f; qb[6]=b4b.y*255.f; qb[7]=b4b.z*255.f; qb[8]=b4b.w*255.f;

    qc[0] = __shfl_up_sync(0xFFFFFFFFu, qc[8], 1);
    qt[0] = __shfl_up_sync(0xFFFFFFFFu, qt[8], 1);
    qb[0] = __shfl_up_sync(0xFFFFFFFFu, qb[8], 1);
    qc[9] = __shfl_down_sync(0xFFFFFFFFu, qc[1], 1);
    qt[9] = __shfl_down_sync(0xFFFFFFFFu, qt[1], 1);
    qb[9] = __shfl_down_sync(0xFFFFFFFFu, qb[1], 1);

    if (lane == 0) {
        const bool hasLeft = (s != 0);
        qc[0] = hasLeft ? rowc[-1] * 255.f : 0.f;
        qt[0] = (hasLeft && hasTop) ? rowt[-1] * 255.f : 0.f;
        qb[0] = (hasLeft && hasBot) ? rowb[-1] * 255.f : 0.f;
    }
    if (lane == 31) {
        const bool hasRight = (s != 1);
        qc[9] = hasRight ? rowc[256] * 255.f : 0.f;
        qt[9] = (hasRight && hasTop) ? rowt[256] * 255.f : 0.f;
        qb[9] = (hasRight && hasBot) ? rowb[256] * 255.f : 0.f;
    }

    float res[8];
#pragma unroll
    for (int j = 0; j < 8; j++) {
        // floor(u)>=floor(v) <=> u>=floor(v); all values non-negative floats,
        // so the float compare equals the signed-int compare of bit patterns.
        const int bc = __float_as_int(floorf(qc[j + 1]));
        // circular order bits 0..7: tl, t, tr, r, br, b, bl, l
        const unsigned d0 = (unsigned)(__float_as_int(qt[j    ]) - bc);
        const unsigned d1 = (unsigned)(__float_as_int(qt[j + 1]) - bc);
        const unsigned d2 = (unsigned)(__float_as_int(qt[j + 2]) - bc);
        const unsigned d3 = (unsigned)(__float_as_int(qc[j + 2]) - bc);
        const unsigned d4 = (unsigned)(__float_as_int(qb[j + 2]) - bc);
        const unsigned d5 = (unsigned)(__float_as_int(qb[j + 1]) - bc);
        const unsigned d6 = (unsigned)(__float_as_int(qb[j    ]) - bc);
        const unsigned d7 = (unsigned)(__float_as_int(qc[j    ]) - bc);
        // prmt sign-replicate: byte = 0xFF where diff<0 (neighbor<center)
        const unsigned sA = prmt(prmt(d0, d1, 0x00FBu),
                                 prmt(d2, d3, 0xFB00u), 0x7610u);
        const unsigned sB = prmt(prmt(d4, d5, 0x00FBu),
                                 prmt(d6, d7, 0xFB00u), 0x7610u);
        // signed dp4a: sign bytes are -1; nibble = 15 - sum(sign*2^i)
        const unsigned mlo = (unsigned)__dp4a((int)sA, 0x08040201, 0x0F);
        const unsigned mhi = (unsigned)__dp4a((int)sB, 0x08040201, 0x0F);
        const unsigned m   = mhi * 16u + mlo;       // single IMAD
        // arithmetic uniform-LBP tail (no memory, no shuffle)
        const unsigned mm  = m * 0x101u;            // m | m<<8 (IMAD)
        const unsigned rot = (mm >> 7) & 0xFFu;     // BFE: circular rot-left-1
        const int trans = __popc(m ^ rot);
        const int ones  = __popc(m);
        const int lbp   = (trans <= 2) ? ones : 9;
        res[j] = (float)lbp * (1.0f / 255.0f);
    }

    float* op = out + (size_t)r * IMG_W + s * 256 + col;
    *reinterpret_cast<float4*>(op)     = make_float4(res[0], res[1], res[2], res[3]);
    *reinterpret_cast<float4*>(op + 4) = make_float4(res[4], res[5], res[6], res[7]);
}

extern "C" void kernel_launch(void* const* d_in, const int* in_sizes, int n_in,
                              void* d_out, int out_size) {
    const float* x = (const float*)d_in[0];
    float* out = (float*)d_out;
    const int nrows  = out_size / IMG_W;   // B*C*H
    const int nwarps = nrows * 2;          // 2 segments of 256 cols
    const int threads = 256;               // 8 warps/block
    const int blocks = (nwarps + 7) / 8;
    lbp_kernel<<<blocks, threads>>>(x, out, nrows);
}